// round 1
// baseline (speedup 1.0000x reference)
#include <cuda_runtime.h>

// Problem constants (from reference)
#define T_LEN  1024
#define BATCH  512
#define HID    64
#define NGATES 256   // 4 * HID

// Scratch for h_t history (device global arrays are the allowed scratch mechanism)
__device__ float g_hbuf[T_LEN * HID];

// ---- packed f32x2 helpers (sm_103a) ----
__device__ __forceinline__ unsigned long long fma2(unsigned long long a,
                                                   unsigned long long b,
                                                   unsigned long long c) {
    unsigned long long d;
    asm("fma.rn.f32x2 %0, %1, %2, %3;" : "=l"(d) : "l"(a), "l"(b), "l"(c));
    return d;
}
__device__ __forceinline__ unsigned long long add2(unsigned long long a,
                                                   unsigned long long b) {
    unsigned long long d;
    asm("add.rn.f32x2 %0, %1, %2;" : "=l"(d) : "l"(a), "l"(b));
    return d;
}

__device__ __forceinline__ float fast_sigmoid(float x) {
    // 1 / (1 + e^-x): EX2 + fast divide. Saturates correctly for |x| large.
    return __fdividef(1.0f, 1.0f + __expf(-x));
}
__device__ __forceinline__ float fast_tanh(float x) {
    // 2 / (1 + e^-2x) - 1
    return __fdividef(2.0f, 1.0f + __expf(-2.0f * x)) - 1.0f;
}

__global__ void __launch_bounds__(256, 1)
lstm_seq_kernel(const float* __restrict__ x,
                const float* __restrict__ W_ih,
                const float* __restrict__ W_hh,
                const float* __restrict__ b_ih,
                const float* __restrict__ b_hh,
                const float* __restrict__ W_fc,
                const float* __restrict__ b_fc,
                float* __restrict__ out)
{
    __shared__ float x_s[T_LEN * 2];                 // x[:, 511, :] preloaded
    __shared__ float ga[NGATES];                     // activated gates
    __shared__ __align__(16) float h_s[HID];         // hidden state broadcast

    const int tid = threadIdx.x;

    // ---- Preload the ONLY batch row that matters: batch index 511 ----
    for (int i = tid; i < T_LEN * 2; i += 256) {
        const int t = i >> 1, c = i & 1;
        x_s[i] = x[(t * BATCH + (BATCH - 1)) * 2 + c];
    }

    // ---- W_hh row `tid` resident in registers, packed as f32x2 pairs ----
    ulonglong2 wr[16];
    {
        const ulonglong2* wsrc =
            reinterpret_cast<const ulonglong2*>(W_hh + tid * HID);
#pragma unroll
        for (int i = 0; i < 16; ++i) wr[i] = wsrc[i];
    }

    const float bj  = b_ih[tid] + b_hh[tid];
    const float wi0 = W_ih[tid * 2 + 0];
    const float wi1 = W_ih[tid * 2 + 1];
    const int   grp = tid >> 6;   // 0:i 1:f 2:g 3:o (uniform per warp)

    float c_state = 0.0f;
    if (tid < HID) h_s[tid] = 0.0f;
    __syncthreads();

    // ---- Sequential recurrence: 1024 steps on one SM ----
    for (int t = 0; t < T_LEN; ++t) {
        const ulonglong2* hv = reinterpret_cast<const ulonglong2*>(h_s);

        // 4 independent packed accumulator chains (breaks FMA RAW chain)
        unsigned long long a0 = 0ull, a1 = 0ull, a2 = 0ull, a3 = 0ull;
#pragma unroll
        for (int i = 0; i < 16; i += 2) {
            const ulonglong2 h0 = hv[i];
            const ulonglong2 h1 = hv[i + 1];
            a0 = fma2(wr[i].x,     h0.x, a0);
            a1 = fma2(wr[i].y,     h0.y, a1);
            a2 = fma2(wr[i + 1].x, h1.x, a2);
            a3 = fma2(wr[i + 1].y, h1.y, a3);
        }
        a0 = add2(a0, a1);
        a2 = add2(a2, a3);
        a0 = add2(a0, a2);

        float lo, hi;
        asm("mov.b64 {%0, %1}, %2;" : "=f"(lo), "=f"(hi) : "l"(a0));

        const float gate =
            fmaf(wi0, x_s[2 * t], fmaf(wi1, x_s[2 * t + 1], bj)) + lo + hi;

        // Activation applied by the owning thread (spreads MUFU work over all 8 warps)
        const float act = (grp == 2) ? fast_tanh(gate) : fast_sigmoid(gate);
        ga[tid] = act;
        __syncthreads();

        if (tid < HID) {
            const float i_ = ga[tid];
            const float f_ = ga[HID + tid];
            const float g_ = ga[2 * HID + tid];
            const float o_ = ga[3 * HID + tid];
            c_state = fmaf(f_, c_state, i_ * g_);
            const float h = o_ * fast_tanh(c_state);
            h_s[tid] = h;
            g_hbuf[t * HID + tid] = h;   // stream h_t for deferred projection
        }
        __syncthreads();
    }

    // ---- Epilogue: out[t, o] = W_fc[o] . h_t + b_fc[o]  (2048 outputs) ----
    // g_hbuf writes are visible block-wide after the final __syncthreads above.
    for (int idx = tid; idx < T_LEN * 2; idx += 256) {
        const int t = idx >> 1, o = idx & 1;
        const float4* hb = reinterpret_cast<const float4*>(g_hbuf + t * HID);
        const float4* wrow = reinterpret_cast<const float4*>(W_fc + o * HID);
        float s = 0.0f;
#pragma unroll
        for (int i = 0; i < 16; ++i) {
            const float4 h4 = hb[i];
            const float4 w4 = wrow[i];
            s = fmaf(h4.x, w4.x, s);
            s = fmaf(h4.y, w4.y, s);
            s = fmaf(h4.z, w4.z, s);
            s = fmaf(h4.w, w4.w, s);
        }
        out[idx] = s + b_fc[o];
    }
}

extern "C" void kernel_launch(void* const* d_in, const int* in_sizes, int n_in,
                              void* d_out, int out_size)
{
    const float* x    = (const float*)d_in[0];
    const float* W_ih = (const float*)d_in[1];
    const float* W_hh = (const float*)d_in[2];
    const float* b_ih = (const float*)d_in[3];
    const float* b_hh = (const float*)d_in[4];
    const float* W_fc = (const float*)d_in[5];
    const float* b_fc = (const float*)d_in[6];
    float* out = (float*)d_out;

    lstm_seq_kernel<<<1, 256>>>(x, W_ih, W_hh, b_ih, b_hh, W_fc, b_fc, out);
}

// round 3
// speedup vs baseline: 1.0738x; 1.0738x over previous
#include <cuda_runtime.h>

#define T_LEN  1024
#define BATCH  512
#define HID    64

// h_t history for the deferred FC projection
__device__ float g_hbuf[T_LEN * HID];

// ---- packed f32x2 helpers (sm_103a) ----
__device__ __forceinline__ unsigned long long fma2(unsigned long long a,
                                                   unsigned long long b,
                                                   unsigned long long c) {
    unsigned long long d;
    asm("fma.rn.f32x2 %0, %1, %2, %3;" : "=l"(d) : "l"(a), "l"(b), "l"(c));
    return d;
}
__device__ __forceinline__ unsigned long long add2(unsigned long long a,
                                                   unsigned long long b) {
    unsigned long long d;
    asm("add.rn.f32x2 %0, %1, %2;" : "=l"(d) : "l"(a), "l"(b));
    return d;
}
__device__ __forceinline__ float ex2f(float x) {
    float r;
    asm("ex2.approx.f32 %0, %1;" : "=f"(r) : "f"(x));
    return r;
}
__device__ __forceinline__ float fast_tanh(float x) {
    // 2/(1+e^-2x) - 1, via ex2 + rcp
    const float k = -2.0f * 1.4426950408889634f; // -2*log2(e)
    return __fdividef(2.0f, 1.0f + ex2f(k * x)) - 1.0f;
}

__global__ void __launch_bounds__(256, 1)
lstm_seq_kernel(const float* __restrict__ x,
                const float* __restrict__ W_ih,
                const float* __restrict__ W_hh,
                const float* __restrict__ b_ih,
                const float* __restrict__ b_hh)
{
    __shared__ float x_s[T_LEN * 2];                    // x[:, 511, :]
    __shared__ __align__(16) float h_s[2][HID];         // double-buffered h

    const int tid = threadIdx.x;
    const int w   = tid >> 5;
    const int l   = tid & 31;
    const int gt  = l >> 3;             // 0:i 1:f 2:g 3:o
    const int u   = (w << 3) | (l & 7); // hidden unit owned by this thread
    const int r   = gt * HID + u;       // gate row in the 256-row weight matrix

    // ---- Preload the only batch row that matters (batch 511) ----
    for (int i = tid; i < T_LEN * 2; i += 256) {
        const int t = i >> 1, c = i & 1;
        x_s[i] = x[(t * BATCH + (BATCH - 1)) * 2 + c];
    }

    // ---- W_hh row r resident in registers as packed f32x2 ----
    ulonglong2 wr[16];
    {
        const ulonglong2* wsrc = reinterpret_cast<const ulonglong2*>(W_hh + r * HID);
#pragma unroll
        for (int i = 0; i < 16; ++i) wr[i] = wsrc[i];
    }

    const float bj  = b_ih[r] + b_hh[r];
    const float wi0 = W_ih[r * 2 + 0];
    const float wi1 = W_ih[r * 2 + 1];

    // Unified activation: act = aoff + bscl * (2/(1+2^(kexp*x)) - 1)
    //   sigmoid: s=0.5 -> aoff=0.5, bscl=0.5 ; tanh: s=1 -> aoff=0, bscl=1
    const bool  is_g  = (gt == 2);
    const float sgain = is_g ? 1.0f : 0.5f;
    const float kexp  = -2.0f * sgain * 1.4426950408889634f;
    const float aoff  = is_g ? 0.0f : 0.5f;
    const float bscl  = is_g ? 1.0f : 0.5f;

    float c_state = 0.0f;
    if (tid < HID) h_s[0][tid] = 0.0f;
    __syncthreads();

    int p = 0;
    for (int t = 0; t < T_LEN; ++t) {
        const ulonglong2* hv = reinterpret_cast<const ulonglong2*>(h_s[p]);

        // 4 independent packed accumulator chains
        unsigned long long a0 = 0ull, a1 = 0ull, a2 = 0ull, a3 = 0ull;
#pragma unroll
        for (int i = 0; i < 16; i += 2) {
            const ulonglong2 h0 = hv[i];
            const ulonglong2 h1 = hv[i + 1];
            a0 = fma2(wr[i].x,     h0.x, a0);
            a1 = fma2(wr[i].y,     h0.y, a1);
            a2 = fma2(wr[i + 1].x, h1.x, a2);
            a3 = fma2(wr[i + 1].y, h1.y, a3);
        }
        a0 = add2(a0, a1);
        a2 = add2(a2, a3);
        a0 = add2(a0, a2);
        float lo, hi;
        asm("mov.b64 {%0, %1}, %2;" : "=f"(lo), "=f"(hi) : "l"(a0));

        const float gate =
            (lo + hi) + fmaf(wi0, x_s[2 * t], fmaf(wi1, x_s[2 * t + 1], bj));

        // Branchless activation
        const float e   = ex2f(kexp * gate);
        const float th  = __fdividef(2.0f, 1.0f + e) - 1.0f;
        const float act = fmaf(bscl, th, aoff);

        // Deliver i, o, f to the g-lane with 3 independent shuffles.
        // g-lane l = 16+u8:  xor16 -> lane u8 (i),  xor8 -> lane 24+u8 (o),
        //                    xor24 -> lane 8+u8 (f)
        const float a16 = __shfl_xor_sync(0xffffffffu, act, 16);
        const float a8  = __shfl_xor_sync(0xffffffffu, act, 8);
        const float a24 = __shfl_xor_sync(0xffffffffu, act, 24);

        if (is_g) {
            // act = g, a16 = i, a8 = o, a24 = f
            c_state = fmaf(a24, c_state, a16 * act);
            const float h = a8 * fast_tanh(c_state);
            h_s[p ^ 1][u] = h;
            g_hbuf[t * HID + u] = h;   // off critical path (STG)
        }
        p ^= 1;
        __syncthreads();
    }
}

// Epilogue: out[t, o] = W_fc[o] . h_t + b_fc[o]   (2048 outputs, 8 CTAs)
__global__ void fc_kernel(const float* __restrict__ W_fc,
                          const float* __restrict__ b_fc,
                          float* __restrict__ out)
{
    const int gid = blockIdx.x * 256 + threadIdx.x;   // 0..2047
    const int t = gid >> 1, o = gid & 1;
    const float4* hb   = reinterpret_cast<const float4*>(g_hbuf + t * HID);
    const float4* wrow = reinterpret_cast<const float4*>(W_fc + o * HID);
    float s = 0.0f;
#pragma unroll
    for (int i = 0; i < 16; ++i) {
        const float4 h4 = hb[i];
        const float4 w4 = wrow[i];
        s = fmaf(h4.x, w4.x, s);
        s = fmaf(h4.y, w4.y, s);
        s = fmaf(h4.z, w4.z, s);
        s = fmaf(h4.w, w4.w, s);
    }
    out[gid] = s + b_fc[o];
}

extern "C" void kernel_launch(void* const* d_in, const int* in_sizes, int n_in,
                              void* d_out, int out_size)
{
    const float* x    = (const float*)d_in[0];
    const float* W_ih = (const float*)d_in[1];
    const float* W_hh = (const float*)d_in[2];
    const float* b_ih = (const float*)d_in[3];
    const float* b_hh = (const float*)d_in[4];
    const float* W_fc = (const float*)d_in[5];
    const float* b_fc = (const float*)d_in[6];
    float* out = (float*)d_out;

    lstm_seq_kernel<<<1, 256>>>(x, W_ih, W_hh, b_ih, b_hh);
    fc_kernel<<<8, 256>>>(W_fc, b_fc, out);
}

// round 4
// speedup vs baseline: 1.3263x; 1.2352x over previous
#include <cuda_runtime.h>

#define T_LEN  1024
#define BATCH  512
#define HID    64

// h_t history for the deferred FC projection
__device__ float g_hbuf[T_LEN * HID];

// ---- packed f32x2 helpers (sm_103a) ----
__device__ __forceinline__ unsigned long long fma2(unsigned long long a,
                                                   unsigned long long b,
                                                   unsigned long long c) {
    unsigned long long d;
    asm("fma.rn.f32x2 %0, %1, %2, %3;" : "=l"(d) : "l"(a), "l"(b), "l"(c));
    return d;
}
__device__ __forceinline__ unsigned long long add2(unsigned long long a,
                                                   unsigned long long b) {
    unsigned long long d;
    asm("add.rn.f32x2 %0, %1, %2;" : "=l"(d) : "l"(a), "l"(b));
    return d;
}
__device__ __forceinline__ float ex2f(float x) {
    float r;
    asm("ex2.approx.f32 %0, %1;" : "=f"(r) : "f"(x));
    return r;
}
__device__ __forceinline__ float fast_tanh(float x) {
    const float k = -2.0f * 1.4426950408889634f;  // -2*log2(e)
    return __fdividef(2.0f, 1.0f + ex2f(k * x)) - 1.0f;
}

// 128 threads, 4 warps. Warp w, lane l: role = l>>4, unit u = w*16 + (l&15).
//   role 0 owns rows: i (u)      and g (128+u)
//   role 1 owns rows: f (64+u)   and o (192+u)
// Each h chunk is loaded ONCE and feeds both rows -> 64 LDS.128/step SM-wide
// (halves the smem-crossbar structural floor vs the 256-thread layout).
__global__ void __launch_bounds__(128, 1)
lstm_seq_kernel(const float* __restrict__ x,
                const float* __restrict__ W_ih,
                const float* __restrict__ W_hh,
                const float* __restrict__ b_ih,
                const float* __restrict__ b_hh)
{
    __shared__ float x_s[T_LEN * 2];
    __shared__ __align__(16) float h_s[2][HID];

    const int tid  = threadIdx.x;
    const int w    = tid >> 5;
    const int l    = tid & 31;
    const int role = l >> 4;               // 0: (i,g)   1: (f,o)
    const int u    = (w << 4) | (l & 15);  // hidden unit 0..63
    const int rA   = role ? (HID + u) : u;            // i or f (both sigmoid)
    const int rB   = role ? (3 * HID + u) : (2 * HID + u);  // g (tanh) or o (sigmoid)

    // ---- Preload the only batch row that matters (batch 511) ----
    for (int i = tid; i < T_LEN * 2; i += 128) {
        const int t = i >> 1, c = i & 1;
        x_s[i] = x[(t * BATCH + (BATCH - 1)) * 2 + c];
    }

    // ---- Two W_hh rows resident in registers as packed f32x2 ----
    ulonglong2 wA[16], wB[16];
    {
        const ulonglong2* sA = reinterpret_cast<const ulonglong2*>(W_hh + rA * HID);
        const ulonglong2* sB = reinterpret_cast<const ulonglong2*>(W_hh + rB * HID);
#pragma unroll
        for (int i = 0; i < 16; ++i) { wA[i] = sA[i]; wB[i] = sB[i]; }
    }

    const float bjA  = b_ih[rA] + b_hh[rA];
    const float bjB  = b_ih[rB] + b_hh[rB];
    const float wiA0 = W_ih[rA * 2], wiA1 = W_ih[rA * 2 + 1];
    const float wiB0 = W_ih[rB * 2], wiB1 = W_ih[rB * 2 + 1];

    // Activation constants. sig(x) = 0.5 + 0.5*tanh(x/2); tanh kept native.
    const float L2E = 1.4426950408889634f;
    const float kA = -L2E;                               // sigmoid
    const float kB = role ? -L2E : -2.0f * L2E;          // role0: tanh, role1: sigmoid
    const float aB = role ? 0.5f : 0.0f;
    const float bB = role ? 0.5f : 1.0f;

    float c_state = 0.0f;
    if (tid < HID) h_s[0][tid] = 0.0f;
    __syncthreads();

    int p = 0;
    for (int t = 0; t < T_LEN; ++t) {
        // x-input terms first (independent of h; overlaps barrier latency)
        const float x0 = x_s[2 * t], x1 = x_s[2 * t + 1];
        float gxA = fmaf(wiA0, x0, fmaf(wiA1, x1, bjA));
        float gxB = fmaf(wiB0, x0, fmaf(wiB1, x1, bjB));

        const ulonglong2* hv = reinterpret_cast<const ulonglong2*>(h_s[p]);

        unsigned long long aA0 = 0ull, aA1 = 0ull, aA2 = 0ull, aA3 = 0ull;
        unsigned long long aB0 = 0ull, aB1 = 0ull, aB2 = 0ull, aB3 = 0ull;
#pragma unroll
        for (int i = 0; i < 16; i += 2) {
            const ulonglong2 h0 = hv[i];
            const ulonglong2 h1 = hv[i + 1];
            aA0 = fma2(wA[i].x,     h0.x, aA0);
            aA1 = fma2(wA[i].y,     h0.y, aA1);
            aA2 = fma2(wA[i + 1].x, h1.x, aA2);
            aA3 = fma2(wA[i + 1].y, h1.y, aA3);
            aB0 = fma2(wB[i].x,     h0.x, aB0);
            aB1 = fma2(wB[i].y,     h0.y, aB1);
            aB2 = fma2(wB[i + 1].x, h1.x, aB2);
            aB3 = fma2(wB[i + 1].y, h1.y, aB3);
        }
        aA0 = add2(aA0, aA1); aA2 = add2(aA2, aA3); aA0 = add2(aA0, aA2);
        aB0 = add2(aB0, aB1); aB2 = add2(aB2, aB3); aB0 = add2(aB0, aB2);

        float loA, hiA, loB, hiB;
        asm("mov.b64 {%0, %1}, %2;" : "=f"(loA), "=f"(hiA) : "l"(aA0));
        asm("mov.b64 {%0, %1}, %2;" : "=f"(loB), "=f"(hiB) : "l"(aB0));

        const float gateA = gxA + (loA + hiA);
        const float gateB = gxB + (loB + hiB);

        // actA: sigmoid(i or f).  actB: tanh(g) for role0, sigmoid(o) for role1.
        const float eA   = ex2f(kA * gateA);
        const float actA = fmaf(0.5f, __fdividef(2.0f, 1.0f + eA) - 1.0f, 0.5f);
        const float eB   = ex2f(kB * gateB);
        const float actB = fmaf(bB, __fdividef(2.0f, 1.0f + eB) - 1.0f, aB);

        // Cross-role exchange (xor 16): role0 sends i*g, role1 sends f and o.
        const float s1 = role ? actA : actA * actB;     // f        | i*g
        const float r1 = __shfl_xor_sync(0xffffffffu, s1, 16);
        const float r2 = __shfl_xor_sync(0xffffffffu, actB, 16);

        const float f_ = role ? actA : r1;
        const float ig = role ? r1   : s1;
        const float o_ = role ? actB : r2;

        // Both roles maintain c redundantly (bit-identical inputs by construction)
        c_state = fmaf(f_, c_state, ig);
        const float h = o_ * fast_tanh(c_state);

        if (role == 0) {
            h_s[p ^ 1][u] = h;
            g_hbuf[t * HID + u] = h;    // off critical path (STG)
        }
        p ^= 1;
        __syncthreads();
    }
}

// Epilogue: out[t, o] = W_fc[o] . h_t + b_fc[o]   (2048 outputs, 8 CTAs)
__global__ void fc_kernel(const float* __restrict__ W_fc,
                          const float* __restrict__ b_fc,
                          float* __restrict__ out)
{
    const int gid = blockIdx.x * 256 + threadIdx.x;   // 0..2047
    const int t = gid >> 1, o = gid & 1;
    const float4* hb   = reinterpret_cast<const float4*>(g_hbuf + t * HID);
    const float4* wrow = reinterpret_cast<const float4*>(W_fc + o * HID);
    float s = 0.0f;
#pragma unroll
    for (int i = 0; i < 16; ++i) {
        const float4 h4 = hb[i];
        const float4 w4 = wrow[i];
        s = fmaf(h4.x, w4.x, s);
        s = fmaf(h4.y, w4.y, s);
        s = fmaf(h4.z, w4.z, s);
        s = fmaf(h4.w, w4.w, s);
    }
    out[gid] = s + b_fc[o];
}

extern "C" void kernel_launch(void* const* d_in, const int* in_sizes, int n_in,
                              void* d_out, int out_size)
{
    const float* x    = (const float*)d_in[0];
    const float* W_ih = (const float*)d_in[1];
    const float* W_hh = (const float*)d_in[2];
    const float* b_ih = (const float*)d_in[3];
    const float* b_hh = (const float*)d_in[4];
    const float* W_fc = (const float*)d_in[5];
    const float* b_fc = (const float*)d_in[6];
    float* out = (float*)d_out;

    lstm_seq_kernel<<<1, 128>>>(x, W_ih, W_hh, b_ih, b_hh);
    fc_kernel<<<8, 256>>>(W_fc, b_fc, out);
}

// round 5
// speedup vs baseline: 1.4311x; 1.0790x over previous
#include <cuda_runtime.h>

#define T_LEN  1024
#define BATCH  512
#define HID    64

__device__ float g_hbuf[T_LEN * HID];

// ---- packed f32x2 + MUFU helpers (sm_103a) ----
__device__ __forceinline__ unsigned long long fma2(unsigned long long a,
                                                   unsigned long long b,
                                                   unsigned long long c) {
    unsigned long long d;
    asm("fma.rn.f32x2 %0, %1, %2, %3;" : "=l"(d) : "l"(a), "l"(b), "l"(c));
    return d;
}
__device__ __forceinline__ unsigned long long add2(unsigned long long a,
                                                   unsigned long long b) {
    unsigned long long d;
    asm("add.rn.f32x2 %0, %1, %2;" : "=l"(d) : "l"(a), "l"(b));
    return d;
}
__device__ __forceinline__ float ex2f(float x) {
    float r; asm("ex2.approx.f32 %0, %1;" : "=f"(r) : "f"(x)); return r;
}
__device__ __forceinline__ float rcpf(float x) {
    float r; asm("rcp.approx.f32 %0, %1;" : "=f"(r) : "f"(x)); return r;
}
__device__ __forceinline__ float tanh_fast(float x) {   // h-path only
    float r; asm("tanh.approx.f32 %0, %1;" : "=f"(r) : "f"(x)); return r;
}

// 128 threads / 4 warps. Warp w, lane l: role = l>>4, unit u = w*16 + (l&15).
//   role 0 owns rows i (u), g (128+u);  role 1 owns rows f (64+u), o (192+u).
__global__ void __launch_bounds__(128, 1)
lstm_seq_kernel(const float* __restrict__ x,
                const float* __restrict__ W_ih,
                const float* __restrict__ W_hh,
                const float* __restrict__ b_ih,
                const float* __restrict__ b_hh)
{
    __shared__ float x_s[T_LEN * 2];
    __shared__ __align__(16) float h_s[2][HID];

    const int tid  = threadIdx.x;
    const int w    = tid >> 5;
    const int l    = tid & 31;
    const int role = l >> 4;
    const int u    = (w << 4) | (l & 15);
    const int rA   = role ? (HID + u) : u;
    const int rB   = role ? (3 * HID + u) : (2 * HID + u);

    for (int i = tid; i < T_LEN * 2; i += 128) {
        const int t = i >> 1, c = i & 1;
        x_s[i] = x[(t * BATCH + (BATCH - 1)) * 2 + c];
    }

    ulonglong2 wA[16], wB[16];
    {
        const ulonglong2* sA = reinterpret_cast<const ulonglong2*>(W_hh + rA * HID);
        const ulonglong2* sB = reinterpret_cast<const ulonglong2*>(W_hh + rB * HID);
#pragma unroll
        for (int i = 0; i < 16; ++i) { wA[i] = sA[i]; wB[i] = sB[i]; }
    }

    const float bjA  = b_ih[rA] + b_hh[rA];
    const float bjB  = b_ih[rB] + b_hh[rB];
    const float wiA0 = W_ih[rA * 2], wiA1 = W_ih[rA * 2 + 1];
    const float wiB0 = W_ih[rB * 2], wiB1 = W_ih[rB * 2 + 1];

    // actA = sigmoid = rcp(1 + 2^(kA*x)).  actB = fma(bB, rcp(1+2^(kB*x)), aB):
    //   role0 (g, tanh): bB=2, aB=-1, kB=-2*L2E ; role1 (o, sigmoid): bB=1, aB=0, kB=-L2E
    const float L2E = 1.4426950408889634f;
    const float kA  = -L2E;
    const float kB  = role ? -L2E : -2.0f * L2E;
    const float aB  = role ? 0.0f : -1.0f;
    const float bB  = role ? 1.0f :  2.0f;

    float c_state = 0.0f;
    if (tid < HID) h_s[0][tid] = 0.0f;
    __syncthreads();

#pragma unroll 1
    for (int t = 0; t < T_LEN; t += 2) {
#pragma unroll
        for (int ph = 0; ph < 2; ++ph) {        // two fully-unrolled phases
            const int tt = t + ph;
            const float x0 = x_s[2 * tt], x1 = x_s[2 * tt + 1];
            const float gxA = fmaf(wiA0, x0, fmaf(wiA1, x1, bjA));
            const float gxB = fmaf(wiB0, x0, fmaf(wiB1, x1, bjB));

            const ulonglong2* hv = reinterpret_cast<const ulonglong2*>(h_s[ph]);

            unsigned long long aA0 = 0ull, aA1 = 0ull, aA2 = 0ull, aA3 = 0ull;
            unsigned long long aB0 = 0ull, aB1 = 0ull, aB2 = 0ull, aB3 = 0ull;
#pragma unroll
            for (int i = 0; i < 16; i += 2) {
                const ulonglong2 h0 = hv[i];
                const ulonglong2 h1 = hv[i + 1];
                aA0 = fma2(wA[i].x,     h0.x, aA0);
                aA1 = fma2(wA[i].y,     h0.y, aA1);
                aA2 = fma2(wA[i + 1].x, h1.x, aA2);
                aA3 = fma2(wA[i + 1].y, h1.y, aA3);
                aB0 = fma2(wB[i].x,     h0.x, aB0);
                aB1 = fma2(wB[i].y,     h0.y, aB1);
                aB2 = fma2(wB[i + 1].x, h1.x, aB2);
                aB3 = fma2(wB[i + 1].y, h1.y, aB3);
            }
            aA0 = add2(aA0, aA1); aA2 = add2(aA2, aA3); aA0 = add2(aA0, aA2);
            aB0 = add2(aB0, aB1); aB2 = add2(aB2, aB3); aB0 = add2(aB0, aB2);

            float loA, hiA, loB, hiB;
            asm("mov.b64 {%0, %1}, %2;" : "=f"(loA), "=f"(hiA) : "l"(aA0));
            asm("mov.b64 {%0, %1}, %2;" : "=f"(loB), "=f"(hiB) : "l"(aB0));

            const float gateA = gxA + (loA + hiA);
            const float gateB = gxB + (loB + hiB);

            // Short-form activations (ex2 + rcp), no trailing arithmetic for sigmoids
            const float actA = rcpf(1.0f + ex2f(kA * gateA));        // i or f
            const float actB = fmaf(bB, rcpf(1.0f + ex2f(kB * gateB)), aB); // g or o

            // role0 sends i*g, role1 sends f; second shfl carries o.
            const float s1 = role ? actA : actA * actB;
            const float r1 = __shfl_xor_sync(0xffffffffu, s1, 16);
            const float r2 = __shfl_xor_sync(0xffffffffu, actB, 16);

            const float f_ = role ? actA : r1;
            const float ig = role ? r1   : s1;
            const float o_ = role ? actB : r2;

            c_state = fmaf(f_, c_state, ig);
            const float h = o_ * tanh_fast(c_state);   // MUFU tanh: -28 cyc on chain

            if (role == 0) {
                h_s[ph ^ 1][u] = h;
                g_hbuf[tt * HID + u] = h;
            }
            __syncthreads();
        }
    }
}

// Epilogue: out[t, o] = W_fc[o] . h_t + b_fc[o]
__global__ void fc_kernel(const float* __restrict__ W_fc,
                          const float* __restrict__ b_fc,
                          float* __restrict__ out)
{
    const int gid = blockIdx.x * 256 + threadIdx.x;
    const int t = gid >> 1, o = gid & 1;
    const float4* hb   = reinterpret_cast<const float4*>(g_hbuf + t * HID);
    const float4* wrow = reinterpret_cast<const float4*>(W_fc + o * HID);
    float s = 0.0f;
#pragma unroll
    for (int i = 0; i < 16; ++i) {
        const float4 h4 = hb[i];
        const float4 w4 = wrow[i];
        s = fmaf(h4.x, w4.x, s);
        s = fmaf(h4.y, w4.y, s);
        s = fmaf(h4.z, w4.z, s);
        s = fmaf(h4.w, w4.w, s);
    }
    out[gid] = s + b_fc[o];
}

extern "C" void kernel_launch(void* const* d_in, const int* in_sizes, int n_in,
                              void* d_out, int out_size)
{
    const float* x    = (const float*)d_in[0];
    const float* W_ih = (const float*)d_in[1];
    const float* W_hh = (const float*)d_in[2];
    const float* b_ih = (const float*)d_in[3];
    const float* b_hh = (const float*)d_in[4];
    const float* W_fc = (const float*)d_in[5];
    const float* b_fc = (const float*)d_in[6];
    float* out = (float*)d_out;

    lstm_seq_kernel<<<1, 128>>>(x, W_ih, W_hh, b_ih, b_hh);
    fc_kernel<<<8, 256>>>(W_fc, b_fc, out);
}

// round 6
// speedup vs baseline: 1.6534x; 1.1554x over previous
#include <cuda_runtime.h>

#define T_LEN  1024
#define BATCH  512
#define HID    64

__device__ float g_hbuf[T_LEN * HID];

// ---- packed f32x2 + MUFU helpers (sm_103a) ----
__device__ __forceinline__ unsigned long long fma2(unsigned long long a,
                                                   unsigned long long b,
                                                   unsigned long long c) {
    unsigned long long d;
    asm("fma.rn.f32x2 %0, %1, %2, %3;" : "=l"(d) : "l"(a), "l"(b), "l"(c));
    return d;
}
__device__ __forceinline__ unsigned long long add2(unsigned long long a,
                                                   unsigned long long b) {
    unsigned long long d;
    asm("add.rn.f32x2 %0, %1, %2;" : "=l"(d) : "l"(a), "l"(b));
    return d;
}
__device__ __forceinline__ unsigned long long pack2(float lo, float hi) {
    unsigned long long d;
    asm("mov.b64 %0, {%1, %2};" : "=l"(d) : "f"(lo), "f"(hi));
    return d;
}
__device__ __forceinline__ float tanh_fast(float x) {
    float r; asm("tanh.approx.f32 %0, %1;" : "=f"(r) : "f"(x)); return r;
}

// 128 threads / 4 warps. Warp w, lane l: role = l>>4, unit u = w*16 + (l&15).
//   role 0 owns rows i (u), g (128+u);  role 1 owns rows f (64+u), o (192+u).
__global__ void __launch_bounds__(128, 1)
lstm_seq_kernel(const float* __restrict__ x,
                const float* __restrict__ W_ih,
                const float* __restrict__ W_hh,
                const float* __restrict__ b_ih,
                const float* __restrict__ b_hh)
{
    __shared__ float x_s[T_LEN * 2];
    __shared__ __align__(16) float h_s[2][HID];

    const int tid  = threadIdx.x;
    const int w    = tid >> 5;
    const int l    = tid & 31;
    const int role = l >> 4;
    const int u    = (w << 4) | (l & 15);
    const int rA   = role ? (HID + u) : u;                  // i | f  (sigmoid)
    const int rB   = role ? (3 * HID + u) : (2 * HID + u);  // g (tanh) | o (sigmoid)

    for (int i = tid; i < T_LEN * 2; i += 128) {
        const int t = i >> 1, c = i & 1;
        x_s[i] = x[(t * BATCH + (BATCH - 1)) * 2 + c];
    }

    ulonglong2 wA[16], wB[16];
    {
        const ulonglong2* sA = reinterpret_cast<const ulonglong2*>(W_hh + rA * HID);
        const ulonglong2* sB = reinterpret_cast<const ulonglong2*>(W_hh + rB * HID);
#pragma unroll
        for (int i = 0; i < 16; ++i) { wA[i] = sA[i]; wB[i] = sB[i]; }
    }

    const float bjA  = b_ih[rA] + b_hh[rA];
    const float bjB  = b_ih[rB] + b_hh[rB];
    const float wiA0 = W_ih[rA * 2], wiA1 = W_ih[rA * 2 + 1];
    const float wiB0 = W_ih[rB * 2], wiB1 = W_ih[rB * 2 + 1];

    // Activations via single MUFU tanh:
    //   sigmoid(x) = 0.5 + 0.5*tanh(0.5x)
    //   actB: role0 -> tanh(x) direct (sB=1, bB=1, aB=0)
    //         role1 -> sigmoid     (sB=0.5, bB=0.5, aB=0.5)
    const float sB = role ? 0.5f : 1.0f;
    const float bB = role ? 0.5f : 1.0f;
    const float aB = role ? 0.5f : 0.0f;

    float c_state = 0.0f;
    if (tid < HID) h_s[0][tid] = 0.0f;
    __syncthreads();

#pragma unroll 1
    for (int t = 0; t < T_LEN; t += 2) {
#pragma unroll
        for (int ph = 0; ph < 2; ++ph) {
            const int tt = t + ph;
            const float x0 = x_s[2 * tt], x1 = x_s[2 * tt + 1];
            const float gxA = fmaf(wiA0, x0, fmaf(wiA1, x1, bjA));
            const float gxB = fmaf(wiB0, x0, fmaf(wiB1, x1, bjB));

            const ulonglong2* hv = reinterpret_cast<const ulonglong2*>(h_s[ph]);

            // Fold the x-input term into the first accumulator (lo lane)
            unsigned long long aA0 = pack2(gxA, 0.0f), aA1 = 0ull, aA2 = 0ull, aA3 = 0ull;
            unsigned long long aB0 = pack2(gxB, 0.0f), aB1 = 0ull, aB2 = 0ull, aB3 = 0ull;
#pragma unroll
            for (int i = 0; i < 16; i += 2) {
                const ulonglong2 h0 = hv[i];
                const ulonglong2 h1 = hv[i + 1];
                aA0 = fma2(wA[i].x,     h0.x, aA0);
                aA1 = fma2(wA[i].y,     h0.y, aA1);
                aA2 = fma2(wA[i + 1].x, h1.x, aA2);
                aA3 = fma2(wA[i + 1].y, h1.y, aA3);
                aB0 = fma2(wB[i].x,     h0.x, aB0);
                aB1 = fma2(wB[i].y,     h0.y, aB1);
                aB2 = fma2(wB[i + 1].x, h1.x, aB2);
                aB3 = fma2(wB[i + 1].y, h1.y, aB3);
            }
            aA0 = add2(aA0, aA1); aA2 = add2(aA2, aA3); aA0 = add2(aA0, aA2);
            aB0 = add2(aB0, aB1); aB2 = add2(aB2, aB3); aB0 = add2(aB0, aB2);

            float loA, hiA, loB, hiB;
            asm("mov.b64 {%0, %1}, %2;" : "=f"(loA), "=f"(hiA) : "l"(aA0));
            asm("mov.b64 {%0, %1}, %2;" : "=f"(loB), "=f"(hiB) : "l"(aB0));

            const float gateA = loA + hiA;   // full preactivation (x-term folded)
            const float gateB = loB + hiB;

            // Single-MUFU activations
            const float actA = fmaf(0.5f, tanh_fast(0.5f * gateA), 0.5f); // i | f
            const float actB = fmaf(bB,   tanh_fast(sB   * gateB), aB);   // g | o

            // ONE shuffle: role0 sends i*g, role1 sends f
            const float send = role ? actA : actA * actB;
            const float recv = __shfl_xor_sync(0xffffffffu, send, 16);

            const float f_ = role ? actA : recv;
            const float ig = role ? recv : send;
            c_state = fmaf(f_, c_state, ig);   // bit-identical in both roles

            // role1 holds o locally -> h has no dependency on a second shuffle
            const float h = actB * tanh_fast(c_state);
            if (role) {
                h_s[ph ^ 1][u] = h;
                g_hbuf[tt * HID + u] = h;
            }
            __syncthreads();
        }
    }
}

// Epilogue: warp-per-timestep butterfly reduction. 1024 warps over 128 CTAs.
__global__ void fc_kernel(const float* __restrict__ W_fc,
                          const float* __restrict__ b_fc,
                          float* __restrict__ out)
{
    const int gtid = blockIdx.x * blockDim.x + threadIdx.x;
    const int t = gtid >> 5;           // 0..1023
    const int l = gtid & 31;

    const float2 h2 = *reinterpret_cast<const float2*>(g_hbuf + t * HID + 2 * l);
    const float2 w0 = *reinterpret_cast<const float2*>(W_fc + 2 * l);
    const float2 w1 = *reinterpret_cast<const float2*>(W_fc + HID + 2 * l);

    float s0 = fmaf(h2.x, w0.x, h2.y * w0.y);
    float s1 = fmaf(h2.x, w1.x, h2.y * w1.y);
#pragma unroll
    for (int o = 16; o; o >>= 1) {
        s0 += __shfl_xor_sync(0xffffffffu, s0, o);
        s1 += __shfl_xor_sync(0xffffffffu, s1, o);
    }
    if (l == 0) {
        out[t * 2 + 0] = s0 + b_fc[0];
        out[t * 2 + 1] = s1 + b_fc[1];
    }
}

extern "C" void kernel_launch(void* const* d_in, const int* in_sizes, int n_in,
                              void* d_out, int out_size)
{
    const float* x    = (const float*)d_in[0];
    const float* W_ih = (const float*)d_in[1];
    const float* W_hh = (const float*)d_in[2];
    const float* b_ih = (const float*)d_in[3];
    const float* b_hh = (const float*)d_in[4];
    const float* W_fc = (const float*)d_in[5];
    const float* b_fc = (const float*)d_in[6];
    float* out = (float*)d_out;

    lstm_seq_kernel<<<1, 128>>>(x, W_ih, W_hh, b_ih, b_hh);
    fc_kernel<<<128, 256>>>(W_fc, b_fc, out);
}

// round 7
// speedup vs baseline: 1.6925x; 1.0237x over previous
#include <cuda_runtime.h>

#define T_LEN  1024
#define BATCH  512
#define HID    64

__device__ float g_hbuf[T_LEN * HID];

// ---- packed f32x2 + MUFU helpers (sm_103a) ----
__device__ __forceinline__ unsigned long long fma2(unsigned long long a,
                                                   unsigned long long b,
                                                   unsigned long long c) {
    unsigned long long d;
    asm("fma.rn.f32x2 %0, %1, %2, %3;" : "=l"(d) : "l"(a), "l"(b), "l"(c));
    return d;
}
__device__ __forceinline__ unsigned long long add2(unsigned long long a,
                                                   unsigned long long b) {
    unsigned long long d;
    asm("add.rn.f32x2 %0, %1, %2;" : "=l"(d) : "l"(a), "l"(b));
    return d;
}
__device__ __forceinline__ unsigned long long pack2(float lo, float hi) {
    unsigned long long d;
    asm("mov.b64 %0, {%1, %2};" : "=l"(d) : "f"(lo), "f"(hi));
    return d;
}
__device__ __forceinline__ float tanh_fast(float x) {
    float r; asm("tanh.approx.f32 %0, %1;" : "=f"(r) : "f"(x)); return r;
}

// 128 threads / 4 warps. Warp w, lane l: role = l>>4, unit u = w*16 + (l&15).
//   role 0 owns rows i (u), g (128+u)   -> produces i*g, sends via shfl
//   role 1 owns rows f (64+u), o (192+u) -> sole owner of c, h
// Sigmoid rows (i, f, o) are pre-scaled by 0.5 so sigmoid = fma(.5, tanh(gate), .5)
// with NO pre-MUFU multiply on the critical path.
__global__ void __launch_bounds__(128, 1)
lstm_seq_kernel(const float* __restrict__ x,
                const float* __restrict__ W_ih,
                const float* __restrict__ W_hh,
                const float* __restrict__ b_ih,
                const float* __restrict__ b_hh,
                const float* __restrict__ W_fc,
                const float* __restrict__ b_fc,
                float* __restrict__ out)
{
    __shared__ float x_s[T_LEN * 2];
    __shared__ __align__(16) float h_s[2][HID];

    const int tid  = threadIdx.x;
    const int w    = tid >> 5;
    const int l    = tid & 31;
    const int role = l >> 4;
    const int u    = (w << 4) | (l & 15);
    const int rA   = role ? (HID + u) : u;                  // i | f  (sigmoid)
    const int rB   = role ? (3 * HID + u) : (2 * HID + u);  // g (tanh) | o (sigmoid)

    for (int i = tid; i < T_LEN * 2; i += 128) {
        const int t = i >> 1, c = i & 1;
        x_s[i] = x[(t * BATCH + (BATCH - 1)) * 2 + c];
    }

    // Pre-scaled weight rows, packed f32x2
    const float sclA = 0.5f;                   // i and f are sigmoids
    const float sclB = role ? 0.5f : 1.0f;     // o sigmoid, g tanh
    ulonglong2 wA[16], wB[16];
    {
        const float4* pA = reinterpret_cast<const float4*>(W_hh + rA * HID);
        const float4* pB = reinterpret_cast<const float4*>(W_hh + rB * HID);
#pragma unroll
        for (int i = 0; i < 16; ++i) {
            const float4 a = pA[i];
            const float4 b = pB[i];
            wA[i].x = pack2(a.x * sclA, a.y * sclA);
            wA[i].y = pack2(a.z * sclA, a.w * sclA);
            wB[i].x = pack2(b.x * sclB, b.y * sclB);
            wB[i].y = pack2(b.z * sclB, b.w * sclB);
        }
    }

    const float bjA  = (b_ih[rA] + b_hh[rA]) * sclA;
    const float bjB  = (b_ih[rB] + b_hh[rB]) * sclB;
    const float wiA0 = W_ih[rA * 2] * sclA, wiA1 = W_ih[rA * 2 + 1] * sclA;
    const float wiB0 = W_ih[rB * 2] * sclB, wiB1 = W_ih[rB * 2 + 1] * sclB;

    const float bB = role ? 0.5f : 1.0f;   // actB = fma(bB, tanh(gateB), aB)
    const float aB = role ? 0.5f : 0.0f;

    float c_state = 0.0f;                  // live only in role1
    if (tid < HID) h_s[0][tid] = 0.0f;
    __syncthreads();

#pragma unroll 1
    for (int t = 0; t < T_LEN; t += 2) {
#pragma unroll
        for (int ph = 0; ph < 2; ++ph) {
            const int tt = t + ph;
            const float x0 = x_s[2 * tt], x1 = x_s[2 * tt + 1];
            const float gxA = fmaf(wiA0, x0, fmaf(wiA1, x1, bjA));
            const float gxB = fmaf(wiB0, x0, fmaf(wiB1, x1, bjB));

            const ulonglong2* hv = reinterpret_cast<const ulonglong2*>(h_s[ph]);

            unsigned long long aA0 = pack2(gxA, 0.0f), aA1 = 0ull, aA2 = 0ull, aA3 = 0ull;
            unsigned long long aB0 = pack2(gxB, 0.0f), aB1 = 0ull, aB2 = 0ull, aB3 = 0ull;
#pragma unroll
            for (int i = 0; i < 16; i += 2) {
                const ulonglong2 h0 = hv[i];
                const ulonglong2 h1 = hv[i + 1];
                aA0 = fma2(wA[i].x,     h0.x, aA0);
                aA1 = fma2(wA[i].y,     h0.y, aA1);
                aA2 = fma2(wA[i + 1].x, h1.x, aA2);
                aA3 = fma2(wA[i + 1].y, h1.y, aA3);
                aB0 = fma2(wB[i].x,     h0.x, aB0);
                aB1 = fma2(wB[i].y,     h0.y, aB1);
                aB2 = fma2(wB[i + 1].x, h1.x, aB2);
                aB3 = fma2(wB[i + 1].y, h1.y, aB3);
            }
            aA0 = add2(aA0, aA1); aA2 = add2(aA2, aA3); aA0 = add2(aA0, aA2);
            aB0 = add2(aB0, aB1); aB2 = add2(aB2, aB3); aB0 = add2(aB0, aB2);

            float loA, hiA, loB, hiB;
            asm("mov.b64 {%0, %1}, %2;" : "=f"(loA), "=f"(hiA) : "l"(aA0));
            asm("mov.b64 {%0, %1}, %2;" : "=f"(loB), "=f"(hiB) : "l"(aB0));

            const float gateA = loA + hiA;   // pre-scaled where sigmoid
            const float gateB = loB + hiB;

            const float actA = fmaf(0.5f, tanh_fast(gateA), 0.5f);  // i | f
            const float actB = fmaf(bB,   tanh_fast(gateB), aB);    // g | o

            // ONE shuffle: role0 sends i*g (role1's send value is ignored)
            const float send = role ? 0.0f : actA * actB;
            const float recv = __shfl_xor_sync(0xffffffffu, send, 16);

            if (role) {
                c_state = fmaf(actA, c_state, recv);   // f*c + i*g
                const float h = actB * tanh_fast(c_state);
                h_s[ph ^ 1][u] = h;
                g_hbuf[tt * HID + u] = h;
            }
            __syncthreads();
        }
    }

    // ---- Fused FC tail: out[t,o] = W_fc[o].h_t + b_fc[o]  (2048 outputs) ----
    // g_hbuf writes above are block-visible after the final __syncthreads.
    {
        const int o     = tid & 1;
        const int tbase = (tid >> 1) * 16;   // 64 pairs x 16 timesteps
        ulonglong2 wf[16];
        {
            const float4* wrow = reinterpret_cast<const float4*>(W_fc + o * HID);
#pragma unroll
            for (int i = 0; i < 16; ++i) {
                const float4 v = wrow[i];
                wf[i].x = pack2(v.x, v.y);
                wf[i].y = pack2(v.z, v.w);
            }
        }
        const float bias = b_fc[o];
#pragma unroll 1
        for (int k = 0; k < 16; ++k) {
            const int tt = tbase + k;
            const ulonglong2* hv =
                reinterpret_cast<const ulonglong2*>(g_hbuf + tt * HID);
            unsigned long long a0 = 0ull, a1 = 0ull, a2 = 0ull, a3 = 0ull;
#pragma unroll
            for (int i = 0; i < 16; i += 2) {
                const ulonglong2 h0 = hv[i];
                const ulonglong2 h1 = hv[i + 1];
                a0 = fma2(wf[i].x,     h0.x, a0);
                a1 = fma2(wf[i].y,     h0.y, a1);
                a2 = fma2(wf[i + 1].x, h1.x, a2);
                a3 = fma2(wf[i + 1].y, h1.y, a3);
            }
            a0 = add2(a0, a1); a2 = add2(a2, a3); a0 = add2(a0, a2);
            float lo, hi;
            asm("mov.b64 {%0, %1}, %2;" : "=f"(lo), "=f"(hi) : "l"(a0));
            out[tt * 2 + o] = (lo + hi) + bias;
        }
    }
}

extern "C" void kernel_launch(void* const* d_in, const int* in_sizes, int n_in,
                              void* d_out, int out_size)
{
    const float* x    = (const float*)d_in[0];
    const float* W_ih = (const float*)d_in[1];
    const float* W_hh = (const float*)d_in[2];
    const float* b_ih = (const float*)d_in[3];
    const float* b_hh = (const float*)d_in[4];
    const float* W_fc = (const float*)d_in[5];
    const float* b_fc = (const float*)d_in[6];
    float* out = (float*)d_out;

    lstm_seq_kernel<<<1, 128>>>(x, W_ih, W_hh, b_ih, b_hh, W_fc, b_fc, out);
}